// round 1
// baseline (speedup 1.0000x reference)
#include <cuda_runtime.h>
#include <math.h>

#define NTASK 16
#define NEMB  25
#define DIM   512
#define HID   1024
#define NTRIP 2000
#define NCPT  64
#define M_ALL (NTASK*NEMB)   // 400
#define GCOLS (3*HID)        // 3072

// ---------------- scratch (static device arrays; no allocation) ----------------
__device__ float    g_G[M_ALL*GCOLS];      // 400 x 3072 = 4.9 MB
__device__ unsigned g_trip[NTASK*NTRIP];   // packed (a | p<<5 | n<<10)
__device__ int      g_cnt[NTASK];
__device__ float    g_q[NTASK*HID];
__device__ float    g_pooled[NTASK*DIM];
__device__ float    g_t1[NTASK*HID];
__device__ float    g_t2[NTASK*DIM];

// ---------------- K1: semihard triplet mining ----------------
__device__ __forceinline__ float warp_sum(float v) {
    #pragma unroll
    for (int o = 16; o > 0; o >>= 1) v += __shfl_xor_sync(0xffffffffu, v, o);
    return v;
}

__global__ __launch_bounds__(256) void mask_kernel(const float* __restrict__ X,
                                                   unsigned* __restrict__ trip,
                                                   int* __restrict__ cnt) {
    int k = blockIdx.x;
    const float* xb = X + k * NEMB * DIM;
    __shared__ float invn[NEMB], sqv[NEMB];
    __shared__ float D[NEMB][NEMB];
    __shared__ int cnt_sh;
    int tid = threadIdx.x, wid = tid >> 5, lane = tid & 31;
    if (tid == 0) cnt_sh = 0;

    // norms
    for (int r = wid; r < NEMB; r += 8) {
        float s = 0.f;
        for (int d = lane; d < DIM; d += 32) { float v = xb[r*DIM + d]; s += v*v; }
        s = warp_sum(s);
        if (lane == 0) invn[r] = rsqrtf(s);
    }
    __syncthreads();
    // sq of normalized rows (matches reference's explicit sum(xn*xn))
    for (int r = wid; r < NEMB; r += 8) {
        float inv = invn[r]; float s = 0.f;
        for (int d = lane; d < DIM; d += 32) { float v = xb[r*DIM + d]*inv; s += v*v; }
        s = warp_sum(s);
        if (lane == 0) sqv[r] = s;
    }
    __syncthreads();
    // pairwise distances (i<j), 300 pairs
    for (int p = wid; p < 300; p += 8) {
        int i = 0, rem = p;
        while (rem >= 24 - i) { rem -= 24 - i; i++; }
        int j = i + 1 + rem;
        float ii = invn[i], ij = invn[j], s = 0.f;
        for (int d = lane; d < DIM; d += 32)
            s += (xb[i*DIM + d]*ii) * (xb[j*DIM + d]*ij);
        s = warp_sum(s);
        if (lane == 0) {
            float d2 = sqv[i] + sqv[j] - 2.f*s;
            float dd = sqrtf(fmaxf(d2, 0.f));
            D[i][j] = dd; D[j][i] = dd;
        }
    }
    __syncthreads();
    // triplets: a (25) x 4 positives x 20 negatives, labels[i] = i % 5
    for (int t = tid; t < NTRIP; t += blockDim.x) {
        int a  = t / 80;
        int rm = t - a*80;
        int pi = rm / 20, ni = rm - (rm/20)*20;
        int lbl = a % 5, ga = a / 5;
        int pg = pi + (pi >= ga ? 1 : 0);
        int p  = lbl + 5*pg;
        int m  = ni >> 2, w = ni & 3;
        int wn = w + (w >= lbl ? 1 : 0);
        int n  = 5*m + wn;
        float tm = D[a][n] - D[a][p];
        if (tm > 0.f && tm <= 0.8f) {
            int pos = atomicAdd(&cnt_sh, 1);
            trip[k*NTRIP + pos] = (unsigned)(a | (p << 5) | (n << 10));
        }
    }
    __syncthreads();
    if (tid == 0) cnt[k] = cnt_sh;
}

// ---------------- K2: G = X[400,512] @ [W1a|W1p|W1n][512,3072] ----------------
// BM=64, BN=64, BK=16, 256 threads, 4x4 per thread
__global__ __launch_bounds__(256) void gemm1_kernel(const float* __restrict__ X,
                                                    const float* __restrict__ W1,
                                                    float* __restrict__ G) {
    __shared__ float As[16][68];   // transposed X tile, padded
    __shared__ float Bs[16][64];
    int tid = threadIdx.x;
    int m0 = blockIdx.y * 64;
    int c0 = blockIdx.x * 64;
    int s  = c0 >> 10;            // which third of W1
    int j0 = c0 & 1023;
    const float* Wb = W1 + (size_t)(s << 9) * 1024 + j0;   // row d -> Wb[d*1024 + jj]
    int tx = tid & 15, ty = tid >> 4;
    int mt = ty << 2, nt = tx << 2;
    float acc[4][4];
    #pragma unroll
    for (int a = 0; a < 4; a++)
        #pragma unroll
        for (int b = 0; b < 4; b++) acc[a][b] = 0.f;

    for (int d0 = 0; d0 < DIM; d0 += 16) {
        // A tile (transposed): 64 rows x 16 cols
        #pragma unroll
        for (int r = 0; r < 4; r++) {
            int m = (tid >> 4) + (r << 4);
            int d = tid & 15;
            int gm = m0 + m;
            float v = (gm < M_ALL) ? X[gm*DIM + d0 + d] : 0.f;
            As[d][m] = v;
        }
        // B tile: 16 rows x 64 cols, float4 per thread
        {
            int kk = tid >> 4;
            int n4 = (tid & 15) << 2;
            float4 v = *reinterpret_cast<const float4*>(Wb + (size_t)(d0 + kk)*1024 + n4);
            *reinterpret_cast<float4*>(&Bs[kk][n4]) = v;
        }
        __syncthreads();
        #pragma unroll
        for (int kk = 0; kk < 16; kk++) {
            float4 av = *reinterpret_cast<const float4*>(&As[kk][mt]);
            float4 bv = *reinterpret_cast<const float4*>(&Bs[kk][nt]);
            float a4[4] = {av.x, av.y, av.z, av.w};
            float b4[4] = {bv.x, bv.y, bv.z, bv.w};
            #pragma unroll
            for (int a = 0; a < 4; a++)
                #pragma unroll
                for (int b = 0; b < 4; b++)
                    acc[a][b] += a4[a] * b4[b];
        }
        __syncthreads();
    }
    #pragma unroll
    for (int r = 0; r < 4; r++) {
        int gm = m0 + mt + r;
        if (gm < M_ALL) {
            float4 v = make_float4(acc[r][0], acc[r][1], acc[r][2], acc[r][3]);
            *reinterpret_cast<float4*>(&G[(size_t)gm*GCOLS + c0 + nt]) = v;
        }
    }
}

// ---------------- K3: q[k,c] = sum over mined triplets of relu(Ga+Gp+Gn+b1) ----
__global__ __launch_bounds__(128) void pool_kernel(const float* __restrict__ G,
                                                   const float* __restrict__ b1,
                                                   const unsigned* __restrict__ trip,
                                                   const int* __restrict__ cnt,
                                                   float* __restrict__ q) {
    int cb = blockIdx.x;   // 8 chunks of 128 cols
    int k  = blockIdx.y;
    __shared__ float sG[3][NEMB][128];
    int tid = threadIdx.x;
    const float* Gt = G + (size_t)k * NEMB * GCOLS;
    for (int idx = tid; idx < 3*NEMB*128; idx += 128) {
        int c = idx & 127;
        int row = idx >> 7;
        int s = row / NEMB, i = row - s*NEMB;
        sG[s][i][c] = Gt[(size_t)i*GCOLS + (s << 10) + (cb << 7) + c];
    }
    __syncthreads();
    int col = (cb << 7) + tid;
    float b1c = b1[col];
    int n = cnt[k];
    const unsigned* tp = trip + k*NTRIP;
    float acc0 = 0.f, acc1 = 0.f;
    int it = 0;
    for (; it + 1 < n; it += 2) {
        unsigned u0 = __ldg(&tp[it]), u1 = __ldg(&tp[it+1]);
        int a0 = u0 & 31, p0 = (u0 >> 5) & 31, n0 = (u0 >> 10) & 31;
        int a1 = u1 & 31, p1 = (u1 >> 5) & 31, n1 = (u1 >> 10) & 31;
        float v0 = sG[0][a0][tid] + sG[1][p0][tid] + sG[2][n0][tid] + b1c;
        float v1 = sG[0][a1][tid] + sG[1][p1][tid] + sG[2][n1][tid] + b1c;
        acc0 += fmaxf(v0, 0.f);
        acc1 += fmaxf(v1, 0.f);
    }
    if (it < n) {
        unsigned u = __ldg(&tp[it]);
        int a = u & 31, p = (u >> 5) & 31, nn = (u >> 10) & 31;
        acc0 += fmaxf(sG[0][a][tid] + sG[1][p][tid] + sG[2][nn][tid] + b1c, 0.f);
    }
    q[k*HID + col] = acc0 + acc1;
}

// ---------------- zero-init for atomic accumulators ----------------
__global__ void zero3_kernel(float* a, int na, float* b, int nb, float* c, int nc) {
    int i = blockIdx.x*blockDim.x + threadIdx.x;
    int st = gridDim.x*blockDim.x;
    for (int t = i; t < na; t += st) a[t] = 0.f;
    for (int t = i; t < nb; t += st) b[t] = 0.f;
    for (int t = i; t < nc; t += st) c[t] = 0.f;
}

// ---------------- head GEMMs: out_acc[16,Nout] += f(in)[16,Nin] @ W ----------
// mode 0: f=identity  | mode 1: f = v + cnt[k]*bvec[i]  | mode 2: f = relu(v + bvec[i])
__global__ __launch_bounds__(256) void headgemm_kernel(const float* __restrict__ in,
                                                       const float* __restrict__ W,
                                                       const float* __restrict__ bvec,
                                                       const int* __restrict__ cnt,
                                                       float* __restrict__ outacc,
                                                       int Nin, int Nout, int ICH, int mode) {
    __shared__ float s_in[16*64];   // max ICH = 64
    int tid = threadIdx.x;
    int jb = blockIdx.x, ib = blockIdx.y;
    int i0 = ib * ICH;
    for (int idx = tid; idx < 16*ICH; idx += 256) {
        int k = idx / ICH, il = idx - k*ICH;
        float v = in[k*Nin + i0 + il];
        if (mode == 1)      v += (float)cnt[k] * bvec[i0 + il];
        else if (mode == 2) v  = fmaxf(v + bvec[i0 + il], 0.f);
        s_in[k*ICH + il] = v;
    }
    __syncthreads();
    int jl = tid & 127, kh = tid >> 7;
    int j = jb*128 + jl;
    float acc[8];
    #pragma unroll
    for (int a = 0; a < 8; a++) acc[a] = 0.f;
    const float4* s4 = (const float4*)s_in;
    int ich4 = ICH >> 2;
    for (int ii = 0; ii < ICH; ii += 4) {
        float w0 = W[(size_t)(i0+ii  )*Nout + j];
        float w1 = W[(size_t)(i0+ii+1)*Nout + j];
        float w2 = W[(size_t)(i0+ii+2)*Nout + j];
        float w3 = W[(size_t)(i0+ii+3)*Nout + j];
        int q4 = ii >> 2;
        #pragma unroll
        for (int kq = 0; kq < 8; kq++) {
            float4 qv = s4[(kh*8 + kq)*ich4 + q4];
            acc[kq] += qv.x*w0 + qv.y*w1 + qv.z*w2 + qv.w*w3;
        }
    }
    #pragma unroll
    for (int kq = 0; kq < 8; kq++)
        atomicAdd(&outacc[(kh*8 + kq)*Nout + j], acc[kq]);
}

// ---------------- final: score = (t2+b4)@Wc + bc, softmax ----------------
__global__ __launch_bounds__(64) void final_kernel(const float* __restrict__ t2,
                                                   const float* __restrict__ b4,
                                                   const float* __restrict__ Wc,
                                                   const float* __restrict__ bc,
                                                   float* __restrict__ out) {
    int k = blockIdx.x, c = threadIdx.x;
    float acc = bc[c];
    const float* tk = t2 + k*DIM;
    for (int i = 0; i < DIM; i++)
        acc += (tk[i] + b4[i]) * Wc[i*NCPT + c];
    __shared__ float sc[NCPT];
    sc[c] = acc; __syncthreads();
    float mx = -1e30f;
    for (int i = 0; i < NCPT; i++) mx = fmaxf(mx, sc[i]);
    float e = expf(acc - mx);
    __syncthreads();
    sc[c] = e; __syncthreads();
    float sum = 0.f;
    for (int i = 0; i < NCPT; i++) sum += sc[i];
    out[k*NCPT + c] = e / sum;
}

// ---------------- launch ----------------
extern "C" void kernel_launch(void* const* d_in, const int* in_sizes, int n_in,
                              void* d_out, int out_size) {
    const float* X  = (const float*)d_in[0];
    const float* W1 = (const float*)d_in[1];
    const float* b1 = (const float*)d_in[2];
    const float* W2 = (const float*)d_in[3];
    const float* b2 = (const float*)d_in[4];
    const float* W3 = (const float*)d_in[5];
    const float* b3 = (const float*)d_in[6];
    const float* W4 = (const float*)d_in[7];
    const float* b4 = (const float*)d_in[8];
    const float* Wc = (const float*)d_in[9];
    const float* bc = (const float*)d_in[10];
    float* out = (float*)d_out;

    float *G, *q, *pooled, *t1, *t2; unsigned* trip; int* cnt;
    cudaGetSymbolAddress((void**)&G,      g_G);
    cudaGetSymbolAddress((void**)&trip,   g_trip);
    cudaGetSymbolAddress((void**)&cnt,    g_cnt);
    cudaGetSymbolAddress((void**)&q,      g_q);
    cudaGetSymbolAddress((void**)&pooled, g_pooled);
    cudaGetSymbolAddress((void**)&t1,     g_t1);
    cudaGetSymbolAddress((void**)&t2,     g_t2);

    mask_kernel<<<NTASK, 256>>>(X, trip, cnt);
    gemm1_kernel<<<dim3(GCOLS/64, (M_ALL + 63)/64), 256>>>(X, W1, G);
    zero3_kernel<<<64, 256>>>(pooled, NTASK*DIM, t1, NTASK*HID, t2, NTASK*DIM);
    pool_kernel<<<dim3(8, NTASK), 128>>>(G, b1, trip, cnt, q);
    // pooled = q @ W2   (cnt*b2 folded into next stage)
    headgemm_kernel<<<dim3(4, 16), 256>>>(q, W2, nullptr, nullptr, pooled, HID, DIM, 64, 0);
    // t1 = (pooled + cnt*b2) @ W3
    headgemm_kernel<<<dim3(8, 16), 256>>>(pooled, W3, b2, cnt, t1, DIM, HID, 32, 1);
    // t2 = relu(t1 + b3) @ W4
    headgemm_kernel<<<dim3(4, 16), 256>>>(t1, W4, b3, nullptr, t2, HID, DIM, 64, 2);
    // score = (t2 + b4) @ Wc + bc, softmax
    final_kernel<<<NTASK, NCPT>>>(t2, b4, Wc, bc, out);
}

// round 2
// speedup vs baseline: 1.6051x; 1.6051x over previous
#include <cuda_runtime.h>
#include <math.h>
#include <stdint.h>

#define NTASK 16
#define NEMB  25
#define DIM   512
#define HID   1024
#define NTRIP 2000
#define NCPT  64
#define M_ALL (NTASK*NEMB)   // 400
#define GCOLS (3*HID)        // 3072

// ---------------- scratch (static device arrays; no allocation) ----------------
__device__ float    g_G[M_ALL*GCOLS];      // 400 x 3072 = 4.9 MB
__device__ unsigned g_trip[NTASK*NTRIP];   // packed (a | p<<5 | n<<10)
__device__ int      g_cnt[NTASK];
__device__ float    g_q[NTASK*HID];
__device__ float    g_pooled[NTASK*DIM];
__device__ float    g_t1[NTASK*HID];
__device__ float    g_t2[NTASK*DIM];

// ---------------- K1: semihard triplet mining ----------------
__device__ __forceinline__ float warp_sum(float v) {
    #pragma unroll
    for (int o = 16; o > 0; o >>= 1) v += __shfl_xor_sync(0xffffffffu, v, o);
    return v;
}

__global__ __launch_bounds__(256) void mask_kernel(const float* __restrict__ X,
                                                   unsigned* __restrict__ trip,
                                                   int* __restrict__ cnt) {
    int k = blockIdx.x;
    const float* xb = X + k * NEMB * DIM;
    __shared__ float invn[NEMB], sqv[NEMB];
    __shared__ float D[NEMB][NEMB];
    __shared__ int cnt_sh;
    int tid = threadIdx.x, wid = tid >> 5, lane = tid & 31;
    if (tid == 0) cnt_sh = 0;

    for (int r = wid; r < NEMB; r += 8) {
        float s = 0.f;
        for (int d = lane; d < DIM; d += 32) { float v = xb[r*DIM + d]; s += v*v; }
        s = warp_sum(s);
        if (lane == 0) invn[r] = rsqrtf(s);
    }
    __syncthreads();
    for (int r = wid; r < NEMB; r += 8) {
        float inv = invn[r]; float s = 0.f;
        for (int d = lane; d < DIM; d += 32) { float v = xb[r*DIM + d]*inv; s += v*v; }
        s = warp_sum(s);
        if (lane == 0) sqv[r] = s;
    }
    __syncthreads();
    for (int p = wid; p < 300; p += 8) {
        int i = 0, rem = p;
        while (rem >= 24 - i) { rem -= 24 - i; i++; }
        int j = i + 1 + rem;
        float ii = invn[i], ij = invn[j], s = 0.f;
        for (int d = lane; d < DIM; d += 32)
            s += (xb[i*DIM + d]*ii) * (xb[j*DIM + d]*ij);
        s = warp_sum(s);
        if (lane == 0) {
            float d2 = sqv[i] + sqv[j] - 2.f*s;
            float dd = sqrtf(fmaxf(d2, 0.f));
            D[i][j] = dd; D[j][i] = dd;
        }
    }
    __syncthreads();
    for (int t = tid; t < NTRIP; t += blockDim.x) {
        int a  = t / 80;
        int rm = t - a*80;
        int pi = rm / 20, ni = rm - (rm/20)*20;
        int lbl = a % 5, ga = a / 5;
        int pg = pi + (pi >= ga ? 1 : 0);
        int p  = lbl + 5*pg;
        int m  = ni >> 2, w = ni & 3;
        int wn = w + (w >= lbl ? 1 : 0);
        int n  = 5*m + wn;
        float tm = D[a][n] - D[a][p];
        if (tm > 0.f && tm <= 0.8f) {
            int pos = atomicAdd(&cnt_sh, 1);
            trip[k*NTRIP + pos] = (unsigned)(a | (p << 5) | (n << 10));
        }
    }
    __syncthreads();
    if (tid == 0) cnt[k] = cnt_sh;
}

// ---------------- K2: tf32 tensor-core GEMM  G = X[400,512] @ W1'[512,3072] ----
// BM=64, BN=128, BK=16, 256 threads (8 warps, 2x4), warp tile 32x32, mma m16n8k8
__device__ __forceinline__ uint32_t tf32r(float f) {
    uint32_t r;
    asm("cvt.rna.tf32.f32 %0, %1;" : "=r"(r) : "f"(f));
    return r;
}

__global__ __launch_bounds__(256) void gemm1_tf32(const float* __restrict__ X,
                                                  const float* __restrict__ W1,
                                                  float* __restrict__ G) {
    __shared__ uint32_t As[16][72];    // [k][m], padded
    __shared__ uint32_t Bs[16][136];   // [k][n], padded
    int tid = threadIdx.x;
    int m0 = blockIdx.y * 64;
    int n0g = blockIdx.x * 128;
    int s  = n0g >> 10;
    int j0 = n0g & 1023;
    const float* Bp = W1 + (size_t)(s << 9) * 1024 + j0;
    int w = tid >> 5, lane = tid & 31;
    int wm = w & 1, wn = w >> 1;            // 2 x 4 warp grid
    int grp = lane >> 2, tid4 = lane & 3;

    float c[2][4][4];
    #pragma unroll
    for (int mt = 0; mt < 2; mt++)
        #pragma unroll
        for (int nt = 0; nt < 4; nt++)
            #pragma unroll
            for (int r = 0; r < 4; r++) c[mt][nt][r] = 0.f;

    // per-thread load coords
    int lam = tid >> 2;            // A: m row 0..63
    int lak = (tid & 3) << 2;      // A: k start (x4)
    int lbr = tid >> 4;            // B: k row 0..15
    int lbc = (tid & 15) << 2;     // B: n start (x4), covers 0..63; +64 second half

    for (int k0 = 0; k0 < DIM; k0 += 16) {
        // A tile: X[m0+m][k0+kk] -> As[kk][m] (tf32-rounded)
        {
            int gm = m0 + lam;
            float4 v = make_float4(0.f, 0.f, 0.f, 0.f);
            if (gm < M_ALL) v = *reinterpret_cast<const float4*>(&X[(size_t)gm*DIM + k0 + lak]);
            As[lak+0][lam] = tf32r(v.x);
            As[lak+1][lam] = tf32r(v.y);
            As[lak+2][lam] = tf32r(v.z);
            As[lak+3][lam] = tf32r(v.w);
        }
        // B tile: W1[(s*512+k0+r)*1024 + j0 + n] -> Bs[r][n]
        {
            const float* src = Bp + (size_t)(k0 + lbr) * 1024;
            float4 v0 = *reinterpret_cast<const float4*>(&src[lbc]);
            float4 v1 = *reinterpret_cast<const float4*>(&src[lbc + 64]);
            Bs[lbr][lbc+0]    = tf32r(v0.x);
            Bs[lbr][lbc+1]    = tf32r(v0.y);
            Bs[lbr][lbc+2]    = tf32r(v0.z);
            Bs[lbr][lbc+3]    = tf32r(v0.w);
            Bs[lbr][lbc+64]   = tf32r(v1.x);
            Bs[lbr][lbc+65]   = tf32r(v1.y);
            Bs[lbr][lbc+66]   = tf32r(v1.z);
            Bs[lbr][lbc+67]   = tf32r(v1.w);
        }
        __syncthreads();
        #pragma unroll
        for (int ks = 0; ks < 16; ks += 8) {
            uint32_t a[2][4], b[4][2];
            #pragma unroll
            for (int mt = 0; mt < 2; mt++) {
                int mr = wm*32 + mt*16 + grp;
                a[mt][0] = As[ks + tid4][mr];
                a[mt][1] = As[ks + tid4][mr + 8];
                a[mt][2] = As[ks + tid4 + 4][mr];
                a[mt][3] = As[ks + tid4 + 4][mr + 8];
            }
            #pragma unroll
            for (int nt = 0; nt < 4; nt++) {
                int nc = wn*32 + nt*8 + grp;
                b[nt][0] = Bs[ks + tid4][nc];
                b[nt][1] = Bs[ks + tid4 + 4][nc];
            }
            #pragma unroll
            for (int mt = 0; mt < 2; mt++)
                #pragma unroll
                for (int nt = 0; nt < 4; nt++) {
                    asm volatile(
                        "mma.sync.aligned.m16n8k8.row.col.f32.tf32.tf32.f32 "
                        "{%0,%1,%2,%3}, {%4,%5,%6,%7}, {%8,%9}, {%0,%1,%2,%3};"
                        : "+f"(c[mt][nt][0]), "+f"(c[mt][nt][1]),
                          "+f"(c[mt][nt][2]), "+f"(c[mt][nt][3])
                        : "r"(a[mt][0]), "r"(a[mt][1]), "r"(a[mt][2]), "r"(a[mt][3]),
                          "r"(b[nt][0]), "r"(b[nt][1]));
                }
        }
        __syncthreads();
    }
    // store
    #pragma unroll
    for (int mt = 0; mt < 2; mt++) {
        int r0 = m0 + wm*32 + mt*16 + grp;
        int r1 = r0 + 8;
        #pragma unroll
        for (int nt = 0; nt < 4; nt++) {
            int col = n0g + wn*32 + nt*8 + 2*tid4;
            if (r0 < M_ALL) {
                G[(size_t)r0*GCOLS + col]     = c[mt][nt][0];
                G[(size_t)r0*GCOLS + col + 1] = c[mt][nt][1];
            }
            if (r1 < M_ALL) {
                G[(size_t)r1*GCOLS + col]     = c[mt][nt][2];
                G[(size_t)r1*GCOLS + col + 1] = c[mt][nt][3];
            }
        }
    }
}

// ---------------- K3: q[k,c] = sum over mined triplets of relu(Ga+Gp+Gn+b1) ----
// 512 threads: 16 warps x (32 lanes * float4 = 128 cols). Warp g strides triplets.
__global__ __launch_bounds__(512) void pool_kernel(const float* __restrict__ G,
                                                   const float* __restrict__ b1,
                                                   const unsigned* __restrict__ trip,
                                                   const int* __restrict__ cnt,
                                                   float* __restrict__ q) {
    int cb = blockIdx.x;   // 8 chunks of 128 cols
    int k  = blockIdx.y;
    __shared__ float4 sG[75][32];    // row = s*25 + i
    __shared__ float4 red[16][32];
    int tid = threadIdx.x, w = tid >> 5, lane = tid & 31;
    const float* Gt = G + (size_t)k * NEMB * GCOLS;
    for (int idx = tid; idx < 75*32; idx += 512) {
        int c = idx & 31, row = idx >> 5;
        int s = row / NEMB, i = row - s*NEMB;
        sG[row][c] = *reinterpret_cast<const float4*>(
            &Gt[(size_t)i*GCOLS + (s << 10) + (cb << 7) + (c << 2)]);
    }
    __syncthreads();
    float4 b1v = *reinterpret_cast<const float4*>(&b1[(cb << 7) + (lane << 2)]);
    int n = cnt[k];
    const unsigned* tp = trip + k*NTRIP;
    float4 acc = make_float4(0.f, 0.f, 0.f, 0.f);
    for (int t = w; t < n; t += 16) {
        unsigned u = __ldg(&tp[t]);
        int a = u & 31, p = (u >> 5) & 31, nn = (u >> 10) & 31;
        float4 va = sG[a][lane];
        float4 vp = sG[25 + p][lane];
        float4 vn = sG[50 + nn][lane];
        acc.x += fmaxf(va.x + vp.x + vn.x + b1v.x, 0.f);
        acc.y += fmaxf(va.y + vp.y + vn.y + b1v.y, 0.f);
        acc.z += fmaxf(va.z + vp.z + vn.z + b1v.z, 0.f);
        acc.w += fmaxf(va.w + vp.w + vn.w + b1v.w, 0.f);
    }
    red[w][lane] = acc;
    __syncthreads();
    if (tid < 32) {
        float4 s = red[0][tid];
        #pragma unroll
        for (int g = 1; g < 16; g++) {
            float4 r = red[g][tid];
            s.x += r.x; s.y += r.y; s.z += r.z; s.w += r.w;
        }
        *reinterpret_cast<float4*>(&q[k*HID + (cb << 7) + (tid << 2)]) = s;
    }
}

// ---------------- zero-init for atomic accumulators ----------------
__global__ void zero3_kernel(float* a, int na, float* b, int nb, float* c, int nc) {
    int i = blockIdx.x*blockDim.x + threadIdx.x;
    int st = gridDim.x*blockDim.x;
    for (int t = i; t < na; t += st) a[t] = 0.f;
    for (int t = i; t < nb; t += st) b[t] = 0.f;
    for (int t = i; t < nc; t += st) c[t] = 0.f;
}

// ---------------- head GEMMs: out_acc[16,Nout] += f(in)[16,Nin] @ W ----------
__global__ __launch_bounds__(256) void headgemm_kernel(const float* __restrict__ in,
                                                       const float* __restrict__ W,
                                                       const float* __restrict__ bvec,
                                                       const int* __restrict__ cnt,
                                                       float* __restrict__ outacc,
                                                       int Nin, int Nout, int ICH, int mode) {
    __shared__ float s_in[16*64];
    int tid = threadIdx.x;
    int jb = blockIdx.x, ib = blockIdx.y;
    int i0 = ib * ICH;
    for (int idx = tid; idx < 16*ICH; idx += 256) {
        int k = idx / ICH, il = idx - k*ICH;
        float v = in[k*Nin + i0 + il];
        if (mode == 1)      v += (float)cnt[k] * bvec[i0 + il];
        else if (mode == 2) v  = fmaxf(v + bvec[i0 + il], 0.f);
        s_in[k*ICH + il] = v;
    }
    __syncthreads();
    int jl = tid & 127, kh = tid >> 7;
    int j = jb*128 + jl;
    float acc[8];
    #pragma unroll
    for (int a = 0; a < 8; a++) acc[a] = 0.f;
    const float4* s4 = (const float4*)s_in;
    int ich4 = ICH >> 2;
    for (int ii = 0; ii < ICH; ii += 4) {
        float w0 = W[(size_t)(i0+ii  )*Nout + j];
        float w1 = W[(size_t)(i0+ii+1)*Nout + j];
        float w2 = W[(size_t)(i0+ii+2)*Nout + j];
        float w3 = W[(size_t)(i0+ii+3)*Nout + j];
        int q4 = ii >> 2;
        #pragma unroll
        for (int kq = 0; kq < 8; kq++) {
            float4 qv = s4[(kh*8 + kq)*ich4 + q4];
            acc[kq] += qv.x*w0 + qv.y*w1 + qv.z*w2 + qv.w*w3;
        }
    }
    #pragma unroll
    for (int kq = 0; kq < 8; kq++)
        atomicAdd(&outacc[(kh*8 + kq)*Nout + j], acc[kq]);
}

// ---------------- final: score = (t2+b4)@Wc + bc, softmax ----------------
__global__ __launch_bounds__(64) void final_kernel(const float* __restrict__ t2,
                                                   const float* __restrict__ b4,
                                                   const float* __restrict__ Wc,
                                                   const float* __restrict__ bc,
                                                   float* __restrict__ out) {
    int k = blockIdx.x, c = threadIdx.x;
    float acc = bc[c];
    const float* tk = t2 + k*DIM;
    for (int i = 0; i < DIM; i++)
        acc += (tk[i] + b4[i]) * Wc[i*NCPT + c];
    __shared__ float sc[NCPT];
    sc[c] = acc; __syncthreads();
    float mx = -1e30f;
    for (int i = 0; i < NCPT; i++) mx = fmaxf(mx, sc[i]);
    float e = expf(acc - mx);
    __syncthreads();
    sc[c] = e; __syncthreads();
    float sum = 0.f;
    for (int i = 0; i < NCPT; i++) sum += sc[i];
    out[k*NCPT + c] = e / sum;
}

// ---------------- launch ----------------
extern "C" void kernel_launch(void* const* d_in, const int* in_sizes, int n_in,
                              void* d_out, int out_size) {
    const float* X  = (const float*)d_in[0];
    const float* W1 = (const float*)d_in[1];
    const float* b1 = (const float*)d_in[2];
    const float* W2 = (const float*)d_in[3];
    const float* b2 = (const float*)d_in[4];
    const float* W3 = (const float*)d_in[5];
    const float* b3 = (const float*)d_in[6];
    const float* W4 = (const float*)d_in[7];
    const float* b4 = (const float*)d_in[8];
    const float* Wc = (const float*)d_in[9];
    const float* bc = (const float*)d_in[10];
    float* out = (float*)d_out;

    float *G, *q, *pooled, *t1, *t2; unsigned* trip; int* cnt;
    cudaGetSymbolAddress((void**)&G,      g_G);
    cudaGetSymbolAddress((void**)&trip,   g_trip);
    cudaGetSymbolAddress((void**)&cnt,    g_cnt);
    cudaGetSymbolAddress((void**)&q,      g_q);
    cudaGetSymbolAddress((void**)&pooled, g_pooled);
    cudaGetSymbolAddress((void**)&t1,     g_t1);
    cudaGetSymbolAddress((void**)&t2,     g_t2);

    mask_kernel<<<NTASK, 256>>>(X, trip, cnt);
    gemm1_tf32<<<dim3(GCOLS/128, (M_ALL + 63)/64), 256>>>(X, W1, G);
    zero3_kernel<<<64, 256>>>(pooled, NTASK*DIM, t1, NTASK*HID, t2, NTASK*DIM);
    pool_kernel<<<dim3(8, NTASK), 512>>>(G, b1, trip, cnt, q);
    headgemm_kernel<<<dim3(4, 16), 256>>>(q, W2, nullptr, nullptr, pooled, HID, DIM, 64, 0);
    headgemm_kernel<<<dim3(8, 16), 256>>>(pooled, W3, b2, cnt, t1, DIM, HID, 32, 1);
    headgemm_kernel<<<dim3(4, 16), 256>>>(t1, W4, b3, nullptr, t2, HID, DIM, 64, 2);
    final_kernel<<<NTASK, NCPT>>>(t2, b4, Wc, bc, out);
}